// round 15
// baseline (speedup 1.0000x reference)
#include <cuda_runtime.h>
#include <cuda_bf16.h>
#include <cstdint>

// ---------------------------------------------------------------------------
// Problem dims
// ---------------------------------------------------------------------------
#define BATCH   4096
#define IN_DIM  1024
#define OUT_DIM 1024
#define KBIG    4096          // 4 * IN_DIM

// GEMM tiling: BM=256, BN=128, 256 threads, warp grid 4x2, warp tile 64x64.
// Two-phase decomposition of the bf16 hi/lo triple product:
//   Phase 1: Ah*Wh + Ah*Wl   (stage {Ah,Wh,Wl} = 64KB, 3 stages)
//   Phase 2: Al*Wh           (stage {Al,Wh}    = 48KB, 4 stages)
// Each phase: single barrier per chunk, loads issued BEFORE compute into the
// stage consumed last iteration -> cp.async issue overlaps MMA.
// Work: 128 tiles x 64 chunks = 8192 units, split into 152 equal ranges per
// phase. Epilogue: atomicAdd onto out (pre-initialized with rank-4 bias).
#define BM 256
#define BN 128
#define BK 64                 // bf16 -> 128 bytes per row
#define NCHUNK (KBIG / BK)    // 64
#define NTILES  128
#define NBLOCKS 152
#define TOTAL_UNITS (NTILES * NCHUNK)   // 8192
#define NTHREADS 256

#define P1_STAGES 3
#define P1_AH 0
#define P1_WH (BM * 128)                  // 32768
#define P1_WL (BM * 128 + BN * 128)       // 49152
#define P1_STAGE_BYTES (BM * 128 + 2 * BN * 128)   // 65536

#define P2_STAGES 4
#define P2_AL 0
#define P2_WH (BM * 128)                  // 32768
#define P2_STAGE_BYTES (BM * 128 + BN * 128)       // 49152

#define SMEM_TOTAL (P1_STAGES * P1_STAGE_BYTES)    // 196608 = 192 KB (>= 4*48KB)

#define SMEM_SWIZZLE_128B(off) ((off) ^ (((off) >> 3) & 0x70))

// ---------------------------------------------------------------------------
// Device scratch (allocation-free rule: __device__ globals)
// ---------------------------------------------------------------------------
__device__ __nv_bfloat16  g_Ah[BATCH * KBIG];         // 32 MB
__device__ __nv_bfloat16  g_Al[BATCH * KBIG];         // 32 MB
__device__ __nv_bfloat16  g_Wh[4 * OUT_DIM * IN_DIM]; // 8 MB
__device__ __nv_bfloat16  g_Wl[4 * OUT_DIM * IN_DIM]; // 8 MB

// ---------------------------------------------------------------------------
// PTX helpers (baseline ISA only)
// ---------------------------------------------------------------------------
__device__ __forceinline__ uint32_t smem_to_u32(const void* p) {
    uint32_t a;
    asm("{ .reg .u64 t; cvta.to.shared.u64 t, %1; cvt.u32.u64 %0, t; }"
        : "=r"(a) : "l"(p));
    return a;
}

__device__ __forceinline__ void cp_async16(uint32_t saddr, const void* gaddr) {
    asm volatile("cp.async.cg.shared.global [%0], [%1], 16;"
                 :: "r"(saddr), "l"(gaddr));
}

#define CP_ASYNC_COMMIT() asm volatile("cp.async.commit_group;" ::: "memory")
#define CP_ASYNC_WAIT1()  asm volatile("cp.async.wait_group 1;" ::: "memory")
#define CP_ASYNC_WAIT2()  asm volatile("cp.async.wait_group 2;" ::: "memory")
#define CP_ASYNC_WAIT0()  asm volatile("cp.async.wait_group 0;" ::: "memory")

__device__ __forceinline__ void ldsm_x4(uint32_t (&r)[4], uint32_t addr) {
    asm volatile("ldmatrix.sync.aligned.m8n8.x4.shared.b16 {%0,%1,%2,%3}, [%4];"
                 : "=r"(r[0]), "=r"(r[1]), "=r"(r[2]), "=r"(r[3]) : "r"(addr));
}

__device__ __forceinline__ void mma_16816(float (&d)[4], const uint32_t (&a)[4],
                                          uint32_t b0, uint32_t b1) {
    asm volatile(
        "mma.sync.aligned.m16n8k16.row.col.f32.bf16.bf16.f32 "
        "{%0,%1,%2,%3}, {%4,%5,%6,%7}, {%8,%9}, {%0,%1,%2,%3};"
        : "+f"(d[0]), "+f"(d[1]), "+f"(d[2]), "+f"(d[3])
        : "r"(a[0]), "r"(a[1]), "r"(a[2]), "r"(a[3]), "r"(b0), "r"(b1));
}

// ---------------------------------------------------------------------------
// Split helpers
// ---------------------------------------------------------------------------
__device__ __forceinline__ uint32_t pack2bf16(__nv_bfloat16 lo, __nv_bfloat16 hi)
{
    return ((uint32_t)__bfloat16_as_ushort(hi) << 16) |
           (uint32_t)__bfloat16_as_ushort(lo);
}

__device__ __forceinline__ void split1(float a, __nv_bfloat16& h, __nv_bfloat16& l)
{
    h = __float2bfloat16(a);
    l = __float2bfloat16(a - __bfloat162float(h));
}

// Split 8 floats (scaled by c) into hi/lo uint4 packs
__device__ __forceinline__ void split8(const float (&v)[8], float c,
                                       uint4& vh, uint4& vl)
{
    __nv_bfloat16 h[8], l[8];
#pragma unroll
    for (int e = 0; e < 8; e++) split1(c * v[e], h[e], l[e]);
    vh = make_uint4(pack2bf16(h[0], h[1]), pack2bf16(h[2], h[3]),
                    pack2bf16(h[4], h[5]), pack2bf16(h[6], h[7]));
    vl = make_uint4(pack2bf16(l[0], l[1]), pack2bf16(l[2], l[3]),
                    pack2bf16(l[4], l[5]), pack2bf16(l[6], l[7]));
}

// ---------------------------------------------------------------------------
// Kernel 1 (merged preprocessing, vectorized 16B stores):
//   blocks [0, 2048):        A split (2 rows/block) + bias init into out
//   blocks [2048, 4096):     W split (8 floats/thread)
// ---------------------------------------------------------------------------
__global__ void __launch_bounds__(256)
prep_kernel(const float* __restrict__ x,
            const float* __restrict__ phase,
            const float* __restrict__ basis,
            const float* __restrict__ w,
            const float* __restrict__ biases,
            float* __restrict__ out)
{
    const int iv = threadIdx.x;

    if (blockIdx.x >= BATCH / 2) {
        // ---- W split: 8 floats per thread, 16B stores ----
        const int blkw = blockIdx.x - BATCH / 2;     // 0..2047
        size_t t8 = (size_t)blkw * 256 + iv;         // 8-float group index
        float4 w0 = reinterpret_cast<const float4*>(w)[t8 * 2];
        float4 w1 = reinterpret_cast<const float4*>(w)[t8 * 2 + 1];
        float v[8] = {w0.x, w0.y, w0.z, w0.w, w1.x, w1.y, w1.z, w1.w};
        uint4 vh, vl;
        split8(v, 1.0f, vh, vl);
        *reinterpret_cast<uint4*>(g_Wh + t8 * 8) = vh;
        *reinterpret_cast<uint4*>(g_Wl + t8 * 8) = vl;
        return;
    }

    // ---- A split + bias init: 2 rows per block, 128 threads per row ----
    const int row = blockIdx.x * 2 + (iv >> 7);
    const int k   = iv & 127;                        // 8-float group within row

    const float HALF_PI = 1.5707963267948966f;
    float r = phase[row] / HALF_PI;
    int q = (int)floorf(r);
    q = min(max(q, 0), 3);
    float t  = r - (float)q;
    float t2 = t * t;
    float t3 = t2 * t;
    float co[4];
#pragma unroll
    for (int kk = 0; kk < 4; kk++)
        co[kk] = t3 * basis[kk] + t2 * basis[4 + kk] + t * basis[8 + kk] + basis[12 + kk];
    float cs[4];
#pragma unroll
    for (int j = 0; j < 4; j++) cs[j] = co[(j - q + 1) & 3];

    float4 x0 = reinterpret_cast<const float4*>(x)[(size_t)row * 256 + k * 2];
    float4 x1 = reinterpret_cast<const float4*>(x)[(size_t)row * 256 + k * 2 + 1];
    float xv[8] = {x0.x, x0.y, x0.z, x0.w, x1.x, x1.y, x1.z, x1.w};

#pragma unroll
    for (int j = 0; j < 4; j++) {
        uint4 vh, vl;
        split8(xv, cs[j], vh, vl);
        size_t base = (size_t)row * KBIG + j * IN_DIM + k * 8;
        *reinterpret_cast<uint4*>(g_Ah + base) = vh;
        *reinterpret_cast<uint4*>(g_Al + base) = vl;
    }

    // out[row, k*8 .. k*8+8) = sum_j cs[j] * biases[j][...]
    {
        int o = k * 8;
        float acc8[8] = {0, 0, 0, 0, 0, 0, 0, 0};
#pragma unroll
        for (int j = 0; j < 4; j++) {
            float4 b0 = *reinterpret_cast<const float4*>(biases + j * OUT_DIM + o);
            float4 b1 = *reinterpret_cast<const float4*>(biases + j * OUT_DIM + o + 4);
            acc8[0] += cs[j] * b0.x; acc8[1] += cs[j] * b0.y;
            acc8[2] += cs[j] * b0.z; acc8[3] += cs[j] * b0.w;
            acc8[4] += cs[j] * b1.x; acc8[5] += cs[j] * b1.y;
            acc8[6] += cs[j] * b1.z; acc8[7] += cs[j] * b1.w;
        }
        float4 r0 = make_float4(acc8[0], acc8[1], acc8[2], acc8[3]);
        float4 r1 = make_float4(acc8[4], acc8[5], acc8[6], acc8[7]);
        *reinterpret_cast<float4*>(out + (size_t)row * OUT_DIM + o) = r0;
        *reinterpret_cast<float4*>(out + (size_t)row * OUT_DIM + o + 4) = r1;
    }
}

// ---------------------------------------------------------------------------
// Kernel 2: two-phase mma.sync bf16 GEMM, 152-way flattened split
// ---------------------------------------------------------------------------
__device__ __forceinline__ void issue_p1(
    uint32_t smem_base, int stage, int ck, int tid, int mBase, int nBase)
{
    const int kA = ck * BK;
    const int j  = kA >> 10;
    const int i0 = kA & (IN_DIM - 1);
    const size_t wOff = (size_t)j * (OUT_DIM * IN_DIM) + i0;
    const uint32_t st = smem_base + stage * P1_STAGE_BYTES;

#pragma unroll
    for (int it = 0; it < 8; it++) {
        int idx = tid + it * NTHREADS;
        int row = idx >> 3;
        int cv  = idx & 7;
        cp_async16(st + P1_AH + SMEM_SWIZZLE_128B(row * 128 + cv * 16),
                   g_Ah + (size_t)(mBase + row) * KBIG + kA + cv * 8);
    }
#pragma unroll
    for (int it = 0; it < 4; it++) {
        int idx = tid + it * NTHREADS;
        int row = idx >> 3;
        int cv  = idx & 7;
        size_t goff = wOff + (size_t)(nBase + row) * IN_DIM + cv * 8;
        uint32_t soff = SMEM_SWIZZLE_128B(row * 128 + cv * 16);
        cp_async16(st + P1_WH + soff, g_Wh + goff);
        cp_async16(st + P1_WL + soff, g_Wl + goff);
    }
}

__device__ __forceinline__ void issue_p2(
    uint32_t smem_base, int stage, int ck, int tid, int mBase, int nBase)
{
    const int kA = ck * BK;
    const int j  = kA >> 10;
    const int i0 = kA & (IN_DIM - 1);
    const size_t wOff = (size_t)j * (OUT_DIM * IN_DIM) + i0;
    const uint32_t st = smem_base + stage * P2_STAGE_BYTES;

#pragma unroll
    for (int it = 0; it < 8; it++) {
        int idx = tid + it * NTHREADS;
        int row = idx >> 3;
        int cv  = idx & 7;
        cp_async16(st + P2_AL + SMEM_SWIZZLE_128B(row * 128 + cv * 16),
                   g_Al + (size_t)(mBase + row) * KBIG + kA + cv * 8);
    }
#pragma unroll
    for (int it = 0; it < 4; it++) {
        int idx = tid + it * NTHREADS;
        int row = idx >> 3;
        int cv  = idx & 7;
        cp_async16(st + P2_WH + SMEM_SWIZZLE_128B(row * 128 + cv * 16),
                   g_Wh + wOff + (size_t)(nBase + row) * IN_DIM + cv * 8);
    }
}

// Phase 1: Ah*Wh + Ah*Wl, 3 stages, single barrier, early issue.
__device__ __forceinline__ void run_p1(
    uint32_t smem_base, int tid, int lane, int wm, int wn,
    int mBase, int nBase, int ck0, int nck, float (&acc)[4][8][4])
{
    const int a_row  = lane & 15;
    const int a_colh = (lane >> 4) * 16;
    const int b_row  = (lane & 7) + ((lane >> 4) << 3);
    const int b_colh = ((lane >> 3) & 1) * 16;
    const int aBase = (wm * 64 + a_row) * 128 + a_colh;
    const int bBase = (wn * 64 + b_row) * 128 + b_colh;

#pragma unroll
    for (int p = 0; p < 2; p++) {
        if (p < nck) issue_p1(smem_base, p, ck0 + p, tid, mBase, nBase);
        CP_ASYNC_COMMIT();
    }

#pragma unroll 1
    for (int i = 0; i < nck; i++) {
        CP_ASYNC_WAIT1();
        __syncthreads();
        {
            int lck = i + 2;
            if (lck < nck)
                issue_p1(smem_base, lck % 3, ck0 + lck, tid, mBase, nBase);
            CP_ASYNC_COMMIT();
        }

        const uint32_t st = smem_base + (i % 3) * P1_STAGE_BYTES;
        const uint32_t sah = st + P1_AH;
        const uint32_t swh = st + P1_WH;
        const uint32_t swl = st + P1_WL;

#pragma unroll
        for (int ks = 0; ks < 4; ks++) {
            const int kc = ks * 32;
            uint32_t aF[4][4];
            uint32_t bH[8][2];
            uint32_t bX[8][2];

#pragma unroll
            for (int mt = 0; mt < 4; mt++)
                ldsm_x4(aF[mt], sah + SMEM_SWIZZLE_128B(aBase + mt * 2048 + kc));
#pragma unroll
            for (int nt2 = 0; nt2 < 4; nt2++) {
                uint32_t b4[4];
                ldsm_x4(b4, swh + SMEM_SWIZZLE_128B(bBase + nt2 * 2048 + kc));
                bH[nt2 * 2 + 0][0] = b4[0]; bH[nt2 * 2 + 0][1] = b4[1];
                bH[nt2 * 2 + 1][0] = b4[2]; bH[nt2 * 2 + 1][1] = b4[3];
            }
#pragma unroll
            for (int mt = 0; mt < 4; mt++)
#pragma unroll
                for (int nt = 0; nt < 8; nt++)
                    mma_16816(acc[mt][nt], aF[mt], bH[nt][0], bH[nt][1]);

#pragma unroll
            for (int nt2 = 0; nt2 < 4; nt2++) {
                uint32_t b4[4];
                ldsm_x4(b4, swl + SMEM_SWIZZLE_128B(bBase + nt2 * 2048 + kc));
                bX[nt2 * 2 + 0][0] = b4[0]; bX[nt2 * 2 + 0][1] = b4[1];
                bX[nt2 * 2 + 1][0] = b4[2]; bX[nt2 * 2 + 1][1] = b4[3];
            }
#pragma unroll
            for (int mt = 0; mt < 4; mt++)
#pragma unroll
                for (int nt = 0; nt < 8; nt++)
                    mma_16816(acc[mt][nt], aF[mt], bX[nt][0], bX[nt][1]);
        }
    }
    CP_ASYNC_WAIT0();
    __syncthreads();
}

// Phase 2: Al*Wh, 4 stages, single barrier, early issue.
__device__ __forceinline__ void run_p2(
    uint32_t smem_base, int tid, int lane, int wm, int wn,
    int mBase, int nBase, int ck0, int nck, float (&acc)[4][8][4])
{
    const int a_row  = lane & 15;
    const int a_colh = (lane >> 4) * 16;
    const int b_row  = (lane & 7) + ((lane >> 4) << 3);
    const int b_colh = ((lane >> 3) & 1) * 16;
    const int aBase = (wm * 64 + a_row) * 128 + a_colh;
    const int bBase = (wn * 64 + b_row) * 128 + b_colh;

#pragma unroll
    for (int p = 0; p < 3; p++) {
        if (p < nck) issue_p2(smem_base, p, ck0 + p, tid, mBase, nBase);
        CP_ASYNC_COMMIT();
    }

#pragma unroll 1
    for (int i = 0; i < nck; i++) {
        CP_ASYNC_WAIT2();
        __syncthreads();
        {
            int lck = i + 3;
            if (lck < nck)
                issue_p2(smem_base, lck & 3, ck0 + lck, tid, mBase, nBase);
            CP_ASYNC_COMMIT();
        }

        const uint32_t st = smem_base + (i & 3) * P2_STAGE_BYTES;
        const uint32_t sal = st + P2_AL;
        const uint32_t swh = st + P2_WH;

#pragma unroll
        for (int ks = 0; ks < 4; ks++) {
            const int kc = ks * 32;
            uint32_t aF[4][4];
            uint32_t bH[8][2];

#pragma unroll
            for (int mt = 0; mt < 4; mt++)
                ldsm_x4(aF[mt], sal + SMEM_SWIZZLE_128B(aBase + mt * 2048 + kc));
#pragma unroll
            for (int nt2 = 0; nt2 < 4; nt2++) {
                uint32_t b4[4];
                ldsm_x4(b4, swh + SMEM_SWIZZLE_128B(bBase + nt2 * 2048 + kc));
                bH[nt2 * 2 + 0][0] = b4[0]; bH[nt2 * 2 + 0][1] = b4[1];
                bH[nt2 * 2 + 1][0] = b4[2]; bH[nt2 * 2 + 1][1] = b4[3];
            }
#pragma unroll
            for (int mt = 0; mt < 4; mt++)
#pragma unroll
                for (int nt = 0; nt < 8; nt++)
                    mma_16816(acc[mt][nt], aF[mt], bH[nt][0], bH[nt][1]);
        }
    }
    CP_ASYNC_WAIT0();
    __syncthreads();
}

__device__ __forceinline__ void atomic_epilogue(
    float* __restrict__ out, const float (&acc)[4][8][4],
    int mBase, int nBase, int wm, int wn, int tg, int tc)
{
#pragma unroll
    for (int nt = 0; nt < 8; nt++) {
        int col = nBase + wn * 64 + nt * 8 + tc;
#pragma unroll
        for (int mt = 0; mt < 4; mt++) {
            int r0 = mBase + wm * 64 + mt * 16 + tg;
            float* p0 = out + (size_t)r0 * OUT_DIM + col;
            float* p1 = out + (size_t)(r0 + 8) * OUT_DIM + col;
            atomicAdd(p0,     acc[mt][nt][0]);
            atomicAdd(p0 + 1, acc[mt][nt][1]);
            atomicAdd(p1,     acc[mt][nt][2]);
            atomicAdd(p1 + 1, acc[mt][nt][3]);
        }
    }
}

__global__ void __launch_bounds__(NTHREADS, 1)
gemm_kernel(float* __restrict__ out)
{
    extern __shared__ char smem[];
    const uint32_t smem_base = smem_to_u32(smem);
    const int tid  = threadIdx.x;
    const int wid  = tid >> 5;
    const int lane = tid & 31;
    const int wm   = wid & 3;    // 4 warp rows (64 rows each)
    const int wn   = wid >> 2;   // 2 warp cols (64 cols each)
    const int tg   = lane >> 2;
    const int tc   = (lane & 3) * 2;

    const int r = blockIdx.x;
    const int lo = (r * TOTAL_UNITS) / NBLOCKS;
    const int hi = ((r + 1) * TOTAL_UNITS) / NBLOCKS;

    float acc[4][8][4];

    // -------- Phase 1: Ah*Wh + Ah*Wl --------
    int u = lo;
#pragma unroll 1
    while (u < hi) {
        const int t     = u >> 6;
        const int c0    = u & 63;
        const int cend  = min(hi - (t << 6), 64);
        const int mBase = (t & 15) * BM;
        const int nBase = (t >> 4) * BN;
#pragma unroll
        for (int i = 0; i < 4; i++)
#pragma unroll
            for (int j = 0; j < 8; j++)
#pragma unroll
                for (int k = 0; k < 4; k++) acc[i][j][k] = 0.f;

        run_p1(smem_base, tid, lane, wm, wn, mBase, nBase, c0, cend - c0, acc);
        atomic_epilogue(out, acc, mBase, nBase, wm, wn, tg, tc);
        u = (t << 6) + cend;
    }

    // -------- Phase 2: Al*Wh --------
    u = lo;
#pragma unroll 1
    while (u < hi) {
        const int t     = u >> 6;
        const int c0    = u & 63;
        const int cend  = min(hi - (t << 6), 64);
        const int mBase = (t & 15) * BM;
        const int nBase = (t >> 4) * BN;
#pragma unroll
        for (int i = 0; i < 4; i++)
#pragma unroll
            for (int j = 0; j < 8; j++)
#pragma unroll
                for (int k = 0; k < 4; k++) acc[i][j][k] = 0.f;

        run_p2(smem_base, tid, lane, wm, wn, mBase, nBase, c0, cend - c0, acc);
        atomic_epilogue(out, acc, mBase, nBase, wm, wn, tg, tc);
        u = (t << 6) + cend;
    }
}

// ---------------------------------------------------------------------------
// kernel_launch
// ---------------------------------------------------------------------------
extern "C" void kernel_launch(void* const* d_in, const int* in_sizes, int n_in,
                              void* d_out, int out_size)
{
    const float* x      = (const float*)d_in[0];
    const float* phase  = (const float*)d_in[1];
    const float* w      = (const float*)d_in[2];
    const float* biases = (const float*)d_in[3];
    const float* basis  = (const float*)d_in[4];
    float* out = (float*)d_out;

    static bool attr_set = false;
    if (!attr_set) {
        cudaFuncSetAttribute(gemm_kernel,
                             cudaFuncAttributeMaxDynamicSharedMemorySize,
                             SMEM_TOTAL);
        attr_set = true;
    }

    prep_kernel<<<BATCH / 2 + 2048, 256>>>(x, phase, basis, w, biases, out);
    gemm_kernel<<<NBLOCKS, NTHREADS, SMEM_TOTAL>>>(out);
}

// round 16
// speedup vs baseline: 1.0647x; 1.0647x over previous
#include <cuda_runtime.h>
#include <cuda_bf16.h>
#include <cstdint>

// ---------------------------------------------------------------------------
// Problem dims
// ---------------------------------------------------------------------------
#define BATCH   4096
#define IN_DIM  1024
#define OUT_DIM 1024
#define KBIG    4096          // 4 * IN_DIM

// GEMM tiling: BM=256, BN=128, 256 threads, warp grid 4x2, warp tile 64x64
// (R14-proven). Fused-3-segment (Ah*Wh + Al*Wh + Ah*Wl).
// Work: 128 tiles x 64 chunks = 8192 units, split into 152 equal contiguous
// ranges. Epilogue: atomicAdd onto out (pre-initialized with rank-4 bias).
#define BM 256
#define BN 128
#define BK 64                 // bf16 -> 128 bytes per row
#define NCHUNK (KBIG / BK)    // 64
#define NTILES  128
#define NBLOCKS 152
#define TOTAL_UNITS (NTILES * NCHUNK)   // 8192
#define STAGES 2
#define NTHREADS 256
#define TILE_AH  0                         // 32 KB
#define TILE_AL  (BM * 128)                // 32 KB
#define TILE_WH  (2 * BM * 128)            // 16 KB
#define TILE_WL  (2 * BM * 128 + BN * 128) // 16 KB
#define STAGE_BYTES  (2 * BM * 128 + 2 * BN * 128)   // 96 KB
#define SMEM_TOTAL   (STAGES * STAGE_BYTES)          // 192 KB

#define SMEM_SWIZZLE_128B(off) ((off) ^ (((off) >> 3) & 0x70))

// ---------------------------------------------------------------------------
// Device scratch (allocation-free rule: __device__ globals)
// ---------------------------------------------------------------------------
__device__ __nv_bfloat16  g_Ah[BATCH * KBIG];         // 32 MB
__device__ __nv_bfloat16  g_Al[BATCH * KBIG];         // 32 MB
__device__ __nv_bfloat16  g_Wh[4 * OUT_DIM * IN_DIM]; // 8 MB
__device__ __nv_bfloat16  g_Wl[4 * OUT_DIM * IN_DIM]; // 8 MB

// ---------------------------------------------------------------------------
// PTX helpers (baseline ISA only)
// ---------------------------------------------------------------------------
__device__ __forceinline__ uint32_t smem_to_u32(const void* p) {
    uint32_t a;
    asm("{ .reg .u64 t; cvta.to.shared.u64 t, %1; cvt.u32.u64 %0, t; }"
        : "=r"(a) : "l"(p));
    return a;
}

__device__ __forceinline__ void cp_async16(uint32_t saddr, const void* gaddr) {
    asm volatile("cp.async.cg.shared.global [%0], [%1], 16;"
                 :: "r"(saddr), "l"(gaddr));
}

#define CP_ASYNC_COMMIT() asm volatile("cp.async.commit_group;" ::: "memory")
#define CP_ASYNC_WAIT1()  asm volatile("cp.async.wait_group 1;" ::: "memory")
#define CP_ASYNC_WAIT0()  asm volatile("cp.async.wait_group 0;" ::: "memory")

__device__ __forceinline__ void ldsm_x4(uint32_t (&r)[4], uint32_t addr) {
    asm volatile("ldmatrix.sync.aligned.m8n8.x4.shared.b16 {%0,%1,%2,%3}, [%4];"
                 : "=r"(r[0]), "=r"(r[1]), "=r"(r[2]), "=r"(r[3]) : "r"(addr));
}

__device__ __forceinline__ void mma_16816(float (&d)[4], const uint32_t (&a)[4],
                                          uint32_t b0, uint32_t b1) {
    asm volatile(
        "mma.sync.aligned.m16n8k16.row.col.f32.bf16.bf16.f32 "
        "{%0,%1,%2,%3}, {%4,%5,%6,%7}, {%8,%9}, {%0,%1,%2,%3};"
        : "+f"(d[0]), "+f"(d[1]), "+f"(d[2]), "+f"(d[3])
        : "r"(a[0]), "r"(a[1]), "r"(a[2]), "r"(a[3]), "r"(b0), "r"(b1));
}

// ---------------------------------------------------------------------------
// Split helpers
// ---------------------------------------------------------------------------
__device__ __forceinline__ uint32_t pack2bf16(__nv_bfloat16 lo, __nv_bfloat16 hi)
{
    return ((uint32_t)__bfloat16_as_ushort(hi) << 16) |
           (uint32_t)__bfloat16_as_ushort(lo);
}

__device__ __forceinline__ void split1(float a, __nv_bfloat16& h, __nv_bfloat16& l)
{
    h = __float2bfloat16(a);
    l = __float2bfloat16(a - __bfloat162float(h));
}

// Split 8 floats (scaled by c) into hi/lo uint4 packs
__device__ __forceinline__ void split8(const float (&v)[8], float c,
                                       uint4& vh, uint4& vl)
{
    __nv_bfloat16 h[8], l[8];
#pragma unroll
    for (int e = 0; e < 8; e++) split1(c * v[e], h[e], l[e]);
    vh = make_uint4(pack2bf16(h[0], h[1]), pack2bf16(h[2], h[3]),
                    pack2bf16(h[4], h[5]), pack2bf16(h[6], h[7]));
    vl = make_uint4(pack2bf16(l[0], l[1]), pack2bf16(l[2], l[3]),
                    pack2bf16(l[4], l[5]), pack2bf16(l[6], l[7]));
}

// ---------------------------------------------------------------------------
// Kernel 1 (merged preprocessing, vectorized 16B stores — R15-validated):
//   blocks [0, 2048):        A split (2 rows/block) + bias init into out
//   blocks [2048, 4096):     W split (8 floats/thread)
// ---------------------------------------------------------------------------
__global__ void __launch_bounds__(256)
prep_kernel(const float* __restrict__ x,
            const float* __restrict__ phase,
            const float* __restrict__ basis,
            const float* __restrict__ w,
            const float* __restrict__ biases,
            float* __restrict__ out)
{
    const int iv = threadIdx.x;

    if (blockIdx.x >= BATCH / 2) {
        // ---- W split: 8 floats per thread, 16B stores ----
        const int blkw = blockIdx.x - BATCH / 2;     // 0..2047
        size_t t8 = (size_t)blkw * 256 + iv;         // 8-float group index
        float4 w0 = reinterpret_cast<const float4*>(w)[t8 * 2];
        float4 w1 = reinterpret_cast<const float4*>(w)[t8 * 2 + 1];
        float v[8] = {w0.x, w0.y, w0.z, w0.w, w1.x, w1.y, w1.z, w1.w};
        uint4 vh, vl;
        split8(v, 1.0f, vh, vl);
        *reinterpret_cast<uint4*>(g_Wh + t8 * 8) = vh;
        *reinterpret_cast<uint4*>(g_Wl + t8 * 8) = vl;
        return;
    }

    // ---- A split + bias init: 2 rows per block, 128 threads per row ----
    const int row = blockIdx.x * 2 + (iv >> 7);
    const int k   = iv & 127;                        // 8-float group within row

    const float HALF_PI = 1.5707963267948966f;
    float r = phase[row] / HALF_PI;
    int q = (int)floorf(r);
    q = min(max(q, 0), 3);
    float t  = r - (float)q;
    float t2 = t * t;
    float t3 = t2 * t;
    float co[4];
#pragma unroll
    for (int kk = 0; kk < 4; kk++)
        co[kk] = t3 * basis[kk] + t2 * basis[4 + kk] + t * basis[8 + kk] + basis[12 + kk];
    float cs[4];
#pragma unroll
    for (int j = 0; j < 4; j++) cs[j] = co[(j - q + 1) & 3];

    float4 x0 = reinterpret_cast<const float4*>(x)[(size_t)row * 256 + k * 2];
    float4 x1 = reinterpret_cast<const float4*>(x)[(size_t)row * 256 + k * 2 + 1];
    float xv[8] = {x0.x, x0.y, x0.z, x0.w, x1.x, x1.y, x1.z, x1.w};

#pragma unroll
    for (int j = 0; j < 4; j++) {
        uint4 vh, vl;
        split8(xv, cs[j], vh, vl);
        size_t base = (size_t)row * KBIG + j * IN_DIM + k * 8;
        *reinterpret_cast<uint4*>(g_Ah + base) = vh;
        *reinterpret_cast<uint4*>(g_Al + base) = vl;
    }

    // out[row, k*8 .. k*8+8) = sum_j cs[j] * biases[j][...]
    {
        int o = k * 8;
        float acc8[8] = {0, 0, 0, 0, 0, 0, 0, 0};
#pragma unroll
        for (int j = 0; j < 4; j++) {
            float4 b0 = *reinterpret_cast<const float4*>(biases + j * OUT_DIM + o);
            float4 b1 = *reinterpret_cast<const float4*>(biases + j * OUT_DIM + o + 4);
            acc8[0] += cs[j] * b0.x; acc8[1] += cs[j] * b0.y;
            acc8[2] += cs[j] * b0.z; acc8[3] += cs[j] * b0.w;
            acc8[4] += cs[j] * b1.x; acc8[5] += cs[j] * b1.y;
            acc8[6] += cs[j] * b1.z; acc8[7] += cs[j] * b1.w;
        }
        float4 r0 = make_float4(acc8[0], acc8[1], acc8[2], acc8[3]);
        float4 r1 = make_float4(acc8[4], acc8[5], acc8[6], acc8[7]);
        *reinterpret_cast<float4*>(out + (size_t)row * OUT_DIM + o) = r0;
        *reinterpret_cast<float4*>(out + (size_t)row * OUT_DIM + o + 4) = r1;
    }
}

// ---------------------------------------------------------------------------
// Kernel 2: fused-3-segment mma.sync bf16 GEMM, 152-way flattened split
// (R14-proven, unchanged)
// ---------------------------------------------------------------------------
__device__ __forceinline__ void issue_tile_load(
    uint32_t smem_base, int stage, int ck, int tid, int mBase, int nBase)
{
    const int kA = ck * BK;
    const int j  = kA >> 10;
    const int i0 = kA & (IN_DIM - 1);
    const size_t wOff = (size_t)j * (OUT_DIM * IN_DIM) + i0;

    const uint32_t st = smem_base + stage * STAGE_BYTES;

#pragma unroll
    for (int it = 0; it < 8; it++) {
        int idx = tid + it * NTHREADS;
        int row = idx >> 3;
        int cv  = idx & 7;
        size_t goff = (size_t)(mBase + row) * KBIG + kA + cv * 8;
        uint32_t soff = SMEM_SWIZZLE_128B(row * 128 + cv * 16);
        cp_async16(st + TILE_AH + soff, g_Ah + goff);
        cp_async16(st + TILE_AL + soff, g_Al + goff);
    }
#pragma unroll
    for (int it = 0; it < 4; it++) {
        int idx = tid + it * NTHREADS;
        int row = idx >> 3;
        int cv  = idx & 7;
        size_t goff = wOff + (size_t)(nBase + row) * IN_DIM + cv * 8;
        uint32_t soff = SMEM_SWIZZLE_128B(row * 128 + cv * 16);
        cp_async16(st + TILE_WH + soff, g_Wh + goff);
        cp_async16(st + TILE_WL + soff, g_Wl + goff);
    }
}

// Run nck chunks [ck0, ck0+nck) of one tile (R10/R14-proven schedule).
__device__ __forceinline__ void run_chunks(
    uint32_t smem_base, int tid, int lane, int wm, int wn,
    int mBase, int nBase, int ck0, int nck, float (&acc)[4][8][4])
{
    const int a_row  = lane & 15;
    const int a_colh = (lane >> 4) * 16;
    const int b_row  = (lane & 7) + ((lane >> 4) << 3);
    const int b_colh = ((lane >> 3) & 1) * 16;

    const int aBase = (wm * 64 + a_row) * 128 + a_colh;
    const int bBase = (wn * 64 + b_row) * 128 + b_colh;

    issue_tile_load(smem_base, 0, ck0, tid, mBase, nBase);
    CP_ASYNC_COMMIT();
    if (nck > 1) issue_tile_load(smem_base, 1, ck0 + 1, tid, mBase, nBase);
    CP_ASYNC_COMMIT();

#pragma unroll 1
    for (int i = 0; i < nck; i++) {
        CP_ASYNC_WAIT1();
        __syncthreads();

        const uint32_t st = smem_base + (i & 1) * STAGE_BYTES;
        const uint32_t sah = st + TILE_AH;
        const uint32_t sal = st + TILE_AL;
        const uint32_t swh = st + TILE_WH;
        const uint32_t swl = st + TILE_WL;

#pragma unroll
        for (int ks = 0; ks < 4; ks++) {
            const int kc = ks * 32;
            uint32_t aF[4][4];     // aH, reused for aL
            uint32_t bH[8][2];
            uint32_t bX[8][2];     // bL

            // step 1: aH, bH -> aH*bH
#pragma unroll
            for (int mt = 0; mt < 4; mt++)
                ldsm_x4(aF[mt], sah + SMEM_SWIZZLE_128B(aBase + mt * 2048 + kc));
#pragma unroll
            for (int nt2 = 0; nt2 < 4; nt2++) {
                uint32_t b4[4];
                ldsm_x4(b4, swh + SMEM_SWIZZLE_128B(bBase + nt2 * 2048 + kc));
                bH[nt2 * 2 + 0][0] = b4[0]; bH[nt2 * 2 + 0][1] = b4[1];
                bH[nt2 * 2 + 1][0] = b4[2]; bH[nt2 * 2 + 1][1] = b4[3];
            }
#pragma unroll
            for (int mt = 0; mt < 4; mt++)
#pragma unroll
                for (int nt = 0; nt < 8; nt++)
                    mma_16816(acc[mt][nt], aF[mt], bH[nt][0], bH[nt][1]);

            // step 2: bL -> aH*bL
#pragma unroll
            for (int nt2 = 0; nt2 < 4; nt2++) {
                uint32_t b4[4];
                ldsm_x4(b4, swl + SMEM_SWIZZLE_128B(bBase + nt2 * 2048 + kc));
                bX[nt2 * 2 + 0][0] = b4[0]; bX[nt2 * 2 + 0][1] = b4[1];
                bX[nt2 * 2 + 1][0] = b4[2]; bX[nt2 * 2 + 1][1] = b4[3];
            }
#pragma unroll
            for (int mt = 0; mt < 4; mt++)
#pragma unroll
                for (int nt = 0; nt < 8; nt++)
                    mma_16816(acc[mt][nt], aF[mt], bX[nt][0], bX[nt][1]);

            // step 3: aL (reuses aF) -> aL*bH
#pragma unroll
            for (int mt = 0; mt < 4; mt++)
                ldsm_x4(aF[mt], sal + SMEM_SWIZZLE_128B(aBase + mt * 2048 + kc));
#pragma unroll
            for (int mt = 0; mt < 4; mt++)
#pragma unroll
                for (int nt = 0; nt < 8; nt++)
                    mma_16816(acc[mt][nt], aF[mt], bH[nt][0], bH[nt][1]);
        }

        __syncthreads();
        {
            int lck = i + STAGES;
            if (lck < nck)
                issue_tile_load(smem_base, i & 1, ck0 + lck, tid, mBase, nBase);
            CP_ASYNC_COMMIT();
        }
    }
    CP_ASYNC_WAIT0();
}

__global__ void __launch_bounds__(NTHREADS, 1)
gemm_kernel(float* __restrict__ out)
{
    extern __shared__ char smem[];
    const uint32_t smem_base = smem_to_u32(smem);
    const int tid  = threadIdx.x;
    const int wid  = tid >> 5;
    const int lane = tid & 31;
    const int wm   = wid & 3;    // 4 warp rows (64 rows each)
    const int wn   = wid >> 2;   // 2 warp cols (64 cols each)
    const int tg   = lane >> 2;
    const int tc   = (lane & 3) * 2;

    const int r = blockIdx.x;
    int u0 = (r * TOTAL_UNITS) / NBLOCKS;
    const int u1 = ((r + 1) * TOTAL_UNITS) / NBLOCKS;

#pragma unroll 1
    while (u0 < u1) {
        const int t     = u0 >> 6;                 // tile index
        const int c0    = u0 & 63;                 // first chunk in tile
        const int cend  = min(u1 - (t << 6), 64);  // end chunk (exclusive)
        const int mBase = (t & 15) * BM;
        const int nBase = (t >> 4) * BN;

        float acc[4][8][4];
#pragma unroll
        for (int i = 0; i < 4; i++)
#pragma unroll
            for (int j = 0; j < 8; j++)
#pragma unroll
                for (int k = 0; k < 4; k++) acc[i][j][k] = 0.f;

        run_chunks(smem_base, tid, lane, wm, wn, mBase, nBase,
                   c0, cend - c0, acc);

        // Atomic-add epilogue (out pre-initialized with bias by prep)
#pragma unroll
        for (int nt = 0; nt < 8; nt++) {
            int col = nBase + wn * 64 + nt * 8 + tc;
#pragma unroll
            for (int mt = 0; mt < 4; mt++) {
                int r0 = mBase + wm * 64 + mt * 16 + tg;
                float* p0 = out + (size_t)r0 * OUT_DIM + col;
                float* p1 = out + (size_t)(r0 + 8) * OUT_DIM + col;
                atomicAdd(p0,     acc[mt][nt][0]);
                atomicAdd(p0 + 1, acc[mt][nt][1]);
                atomicAdd(p1,     acc[mt][nt][2]);
                atomicAdd(p1 + 1, acc[mt][nt][3]);
            }
        }
        __syncthreads();   // all warps done before next segment reuses smem
        u0 = (t << 6) + cend;
    }
}

// ---------------------------------------------------------------------------
// kernel_launch
// ---------------------------------------------------------------------------
extern "C" void kernel_launch(void* const* d_in, const int* in_sizes, int n_in,
                              void* d_out, int out_size)
{
    const float* x      = (const float*)d_in[0];
    const float* phase  = (const float*)d_in[1];
    const float* w      = (const float*)d_in[2];
    const float* biases = (const float*)d_in[3];
    const float* basis  = (const float*)d_in[4];
    float* out = (float*)d_out;

    static bool attr_set = false;
    if (!attr_set) {
        cudaFuncSetAttribute(gemm_kernel,
                             cudaFuncAttributeMaxDynamicSharedMemorySize,
                             SMEM_TOTAL);
        attr_set = true;
    }

    prep_kernel<<<BATCH / 2 + 2048, 256>>>(x, phase, basis, w, biases, out);
    gemm_kernel<<<NBLOCKS, NTHREADS, SMEM_TOTAL>>>(out);
}

// round 17
// speedup vs baseline: 2.4843x; 2.3332x over previous
#include <cuda_runtime.h>
#include <cuda_fp16.h>
#include <cstdint>

// ---------------------------------------------------------------------------
// Problem dims
// ---------------------------------------------------------------------------
#define BATCH   4096
#define IN_DIM  1024
#define OUT_DIM 1024
#define KBIG    4096          // 4 * IN_DIM

// Single-product FP16 GEMM: D = A_fp16 * W_fp16 (f32 accumulate).
// Input-rounding error ~4e-4 (norm), well under the 1e-3 gate; products are
// exact inside HMMA, accumulation is f32.
// Tiling: BM=256, BN=128, BK=64 (fp16 -> 128-byte rows, SW128), 256 threads,
// warp grid 4x2, warp tile 64x64. 4 stages x 48KB, ONE barrier per chunk,
// loads issued early into the stage consumed last iteration.
// Work: 128 tiles x 64 chunks = 8192 units -> 152 equal contiguous ranges.
// Epilogue: atomicAdd onto out (pre-initialized with rank-4 bias by prep).
#define BM 256
#define BN 128
#define BK 64
#define NCHUNK (KBIG / BK)    // 64
#define NTILES  128
#define NBLOCKS 152
#define TOTAL_UNITS (NTILES * NCHUNK)   // 8192
#define STAGES 4
#define NTHREADS 256
#define TILE_A   0                        // 32 KB (256 rows x 128 B)
#define TILE_W   (BM * 128)               // 16 KB (128 rows x 128 B)
#define STAGE_BYTES  (BM * 128 + BN * 128)   // 48 KB
#define SMEM_TOTAL   (STAGES * STAGE_BYTES)  // 192 KB

#define SMEM_SWIZZLE_128B(off) ((off) ^ (((off) >> 3) & 0x70))

// ---------------------------------------------------------------------------
// Device scratch (allocation-free rule: __device__ globals)
// ---------------------------------------------------------------------------
__device__ __half  g_A[BATCH * KBIG];          // 32 MB
__device__ __half  g_W[4 * OUT_DIM * IN_DIM];  // 8 MB

// ---------------------------------------------------------------------------
// PTX helpers (baseline ISA only)
// ---------------------------------------------------------------------------
__device__ __forceinline__ uint32_t smem_to_u32(const void* p) {
    uint32_t a;
    asm("{ .reg .u64 t; cvta.to.shared.u64 t, %1; cvt.u32.u64 %0, t; }"
        : "=r"(a) : "l"(p));
    return a;
}

__device__ __forceinline__ void cp_async16(uint32_t saddr, const void* gaddr) {
    asm volatile("cp.async.cg.shared.global [%0], [%1], 16;"
                 :: "r"(saddr), "l"(gaddr));
}

#define CP_ASYNC_COMMIT() asm volatile("cp.async.commit_group;" ::: "memory")
#define CP_ASYNC_WAIT2()  asm volatile("cp.async.wait_group 2;" ::: "memory")
#define CP_ASYNC_WAIT0()  asm volatile("cp.async.wait_group 0;" ::: "memory")

__device__ __forceinline__ void ldsm_x4(uint32_t (&r)[4], uint32_t addr) {
    asm volatile("ldmatrix.sync.aligned.m8n8.x4.shared.b16 {%0,%1,%2,%3}, [%4];"
                 : "=r"(r[0]), "=r"(r[1]), "=r"(r[2]), "=r"(r[3]) : "r"(addr));
}

__device__ __forceinline__ void mma_16816(float (&d)[4], const uint32_t (&a)[4],
                                          uint32_t b0, uint32_t b1) {
    asm volatile(
        "mma.sync.aligned.m16n8k16.row.col.f32.f16.f16.f32 "
        "{%0,%1,%2,%3}, {%4,%5,%6,%7}, {%8,%9}, {%0,%1,%2,%3};"
        : "+f"(d[0]), "+f"(d[1]), "+f"(d[2]), "+f"(d[3])
        : "r"(a[0]), "r"(a[1]), "r"(a[2]), "r"(a[3]), "r"(b0), "r"(b1));
}

// ---------------------------------------------------------------------------
// fp16 pack helpers
// ---------------------------------------------------------------------------
__device__ __forceinline__ uint32_t pack2h(__half lo, __half hi)
{
    return ((uint32_t)__half_as_ushort(hi) << 16) |
           (uint32_t)__half_as_ushort(lo);
}

__device__ __forceinline__ uint4 pack8h(const float (&v)[8], float c)
{
    __half h[8];
#pragma unroll
    for (int e = 0; e < 8; e++) h[e] = __float2half_rn(c * v[e]);
    return make_uint4(pack2h(h[0], h[1]), pack2h(h[2], h[3]),
                      pack2h(h[4], h[5]), pack2h(h[6], h[7]));
}

// ---------------------------------------------------------------------------
// Kernel 1 (merged preprocessing):
//   blocks [0, 2048):        A = c_eff * x -> fp16 (2 rows/block) + bias init
//   blocks [2048, 4096):     W -> fp16 (8 floats/thread)
// ---------------------------------------------------------------------------
__global__ void __launch_bounds__(256)
prep_kernel(const float* __restrict__ x,
            const float* __restrict__ phase,
            const float* __restrict__ basis,
            const float* __restrict__ w,
            const float* __restrict__ biases,
            float* __restrict__ out)
{
    const int iv = threadIdx.x;

    if (blockIdx.x >= BATCH / 2) {
        // ---- W convert: 8 floats per thread, one 16B store ----
        const int blkw = blockIdx.x - BATCH / 2;     // 0..2047
        size_t t8 = (size_t)blkw * 256 + iv;         // 8-float group index
        float4 w0 = reinterpret_cast<const float4*>(w)[t8 * 2];
        float4 w1 = reinterpret_cast<const float4*>(w)[t8 * 2 + 1];
        float v[8] = {w0.x, w0.y, w0.z, w0.w, w1.x, w1.y, w1.z, w1.w};
        *reinterpret_cast<uint4*>(g_W + t8 * 8) = pack8h(v, 1.0f);
        return;
    }

    // ---- A convert + bias init: 2 rows per block, 128 threads per row ----
    const int row = blockIdx.x * 2 + (iv >> 7);
    const int k   = iv & 127;                        // 8-float group within row

    const float HALF_PI = 1.5707963267948966f;
    float r = phase[row] / HALF_PI;
    int q = (int)floorf(r);
    q = min(max(q, 0), 3);
    float t  = r - (float)q;
    float t2 = t * t;
    float t3 = t2 * t;
    float co[4];
#pragma unroll
    for (int kk = 0; kk < 4; kk++)
        co[kk] = t3 * basis[kk] + t2 * basis[4 + kk] + t * basis[8 + kk] + basis[12 + kk];
    float cs[4];
#pragma unroll
    for (int j = 0; j < 4; j++) cs[j] = co[(j - q + 1) & 3];

    float4 x0 = reinterpret_cast<const float4*>(x)[(size_t)row * 256 + k * 2];
    float4 x1 = reinterpret_cast<const float4*>(x)[(size_t)row * 256 + k * 2 + 1];
    float xv[8] = {x0.x, x0.y, x0.z, x0.w, x1.x, x1.y, x1.z, x1.w};

#pragma unroll
    for (int j = 0; j < 4; j++) {
        size_t base = (size_t)row * KBIG + j * IN_DIM + k * 8;
        *reinterpret_cast<uint4*>(g_A + base) = pack8h(xv, cs[j]);
    }

    // out[row, k*8 .. k*8+8) = sum_j cs[j] * biases[j][...]
    {
        int o = k * 8;
        float acc8[8] = {0, 0, 0, 0, 0, 0, 0, 0};
#pragma unroll
        for (int j = 0; j < 4; j++) {
            float4 b0 = *reinterpret_cast<const float4*>(biases + j * OUT_DIM + o);
            float4 b1 = *reinterpret_cast<const float4*>(biases + j * OUT_DIM + o + 4);
            acc8[0] += cs[j] * b0.x; acc8[1] += cs[j] * b0.y;
            acc8[2] += cs[j] * b0.z; acc8[3] += cs[j] * b0.w;
            acc8[4] += cs[j] * b1.x; acc8[5] += cs[j] * b1.y;
            acc8[6] += cs[j] * b1.z; acc8[7] += cs[j] * b1.w;
        }
        float4 r0 = make_float4(acc8[0], acc8[1], acc8[2], acc8[3]);
        float4 r1 = make_float4(acc8[4], acc8[5], acc8[6], acc8[7]);
        *reinterpret_cast<float4*>(out + (size_t)row * OUT_DIM + o) = r0;
        *reinterpret_cast<float4*>(out + (size_t)row * OUT_DIM + o + 4) = r1;
    }
}

// ---------------------------------------------------------------------------
// Kernel 2: single-product fp16 GEMM, 4-stage single-barrier pipeline,
// 152-way flattened work split, atomicAdd epilogue
// ---------------------------------------------------------------------------
__device__ __forceinline__ void issue_tile_load(
    uint32_t smem_base, int stage, int ck, int tid, int mBase, int nBase)
{
    const int kA = ck * BK;
    const int j  = kA >> 10;
    const int i0 = kA & (IN_DIM - 1);
    const size_t wOff = (size_t)j * (OUT_DIM * IN_DIM) + i0;

    const uint32_t st = smem_base + stage * STAGE_BYTES;

    // A: 256 rows x 8 vec16 = 2048 vectors -> 8 per thread
#pragma unroll
    for (int it = 0; it < 8; it++) {
        int idx = tid + it * NTHREADS;
        int row = idx >> 3;
        int cv  = idx & 7;
        cp_async16(st + TILE_A + SMEM_SWIZZLE_128B(row * 128 + cv * 16),
                   g_A + (size_t)(mBase + row) * KBIG + kA + cv * 8);
    }
    // W: 128 rows x 8 vec16 = 1024 vectors -> 4 per thread
#pragma unroll
    for (int it = 0; it < 4; it++) {
        int idx = tid + it * NTHREADS;
        int row = idx >> 3;
        int cv  = idx & 7;
        cp_async16(st + TILE_W + SMEM_SWIZZLE_128B(row * 128 + cv * 16),
                   g_W + wOff + (size_t)(nBase + row) * IN_DIM + cv * 8);
    }
}

// Run nck chunks [ck0, ck0+nck). 4 stages; per iteration:
//   wait(2) -> ONE sync -> issue chunk i+3 into stage (i+3)&3 (consumed at
//   iteration i-1, so free once the sync passes) -> compute.
__device__ __forceinline__ void run_chunks(
    uint32_t smem_base, int tid, int lane, int wm, int wn,
    int mBase, int nBase, int ck0, int nck, float (&acc)[4][8][4])
{
    const int a_row  = lane & 15;
    const int a_colh = (lane >> 4) * 16;
    const int b_row  = (lane & 7) + ((lane >> 4) << 3);
    const int b_colh = ((lane >> 3) & 1) * 16;

    const int aBase = (wm * 64 + a_row) * 128 + a_colh;
    const int bBase = (wn * 64 + b_row) * 128 + b_colh;

    // Prologue: up to 3 chunks in flight (commit unconditionally for count)
#pragma unroll
    for (int p = 0; p < 3; p++) {
        if (p < nck) issue_tile_load(smem_base, p, ck0 + p, tid, mBase, nBase);
        CP_ASYNC_COMMIT();
    }

#pragma unroll 1
    for (int i = 0; i < nck; i++) {
        CP_ASYNC_WAIT2();          // chunk i's group complete
        __syncthreads();           // all warps past compute of i-1

        {
            int lck = i + 3;
            if (lck < nck)
                issue_tile_load(smem_base, lck & 3, ck0 + lck, tid, mBase, nBase);
            CP_ASYNC_COMMIT();
        }

        const uint32_t st = smem_base + (i & 3) * STAGE_BYTES;
        const uint32_t sa = st + TILE_A;
        const uint32_t sw = st + TILE_W;

#pragma unroll
        for (int ks = 0; ks < 4; ks++) {
            const int kc = ks * 32;
            uint32_t aF[4][4];
            uint32_t bF[8][2];

#pragma unroll
            for (int mt = 0; mt < 4; mt++)
                ldsm_x4(aF[mt], sa + SMEM_SWIZZLE_128B(aBase + mt * 2048 + kc));
#pragma unroll
            for (int nt2 = 0; nt2 < 4; nt2++) {
                uint32_t b4[4];
                ldsm_x4(b4, sw + SMEM_SWIZZLE_128B(bBase + nt2 * 2048 + kc));
                bF[nt2 * 2 + 0][0] = b4[0]; bF[nt2 * 2 + 0][1] = b4[1];
                bF[nt2 * 2 + 1][0] = b4[2]; bF[nt2 * 2 + 1][1] = b4[3];
            }
#pragma unroll
            for (int mt = 0; mt < 4; mt++)
#pragma unroll
                for (int nt = 0; nt < 8; nt++)
                    mma_16816(acc[mt][nt], aF[mt], bF[nt][0], bF[nt][1]);
        }
    }
    CP_ASYNC_WAIT0();
}

__global__ void __launch_bounds__(NTHREADS, 1)
gemm_kernel(float* __restrict__ out)
{
    extern __shared__ char smem[];
    const uint32_t smem_base = smem_to_u32(smem);
    const int tid  = threadIdx.x;
    const int wid  = tid >> 5;
    const int lane = tid & 31;
    const int wm   = wid & 3;    // 4 warp rows (64 rows each)
    const int wn   = wid >> 2;   // 2 warp cols (64 cols each)
    const int tg   = lane >> 2;
    const int tc   = (lane & 3) * 2;

    const int r = blockIdx.x;
    int u0 = (r * TOTAL_UNITS) / NBLOCKS;
    const int u1 = ((r + 1) * TOTAL_UNITS) / NBLOCKS;

#pragma unroll 1
    while (u0 < u1) {
        const int t     = u0 >> 6;                 // tile index
        const int c0    = u0 & 63;                 // first chunk in tile
        const int cend  = min(u1 - (t << 6), 64);  // end chunk (exclusive)
        const int mBase = (t & 15) * BM;
        const int nBase = (t >> 4) * BN;

        float acc[4][8][4];
#pragma unroll
        for (int i = 0; i < 4; i++)
#pragma unroll
            for (int j = 0; j < 8; j++)
#pragma unroll
                for (int k = 0; k < 4; k++) acc[i][j][k] = 0.f;

        run_chunks(smem_base, tid, lane, wm, wn, mBase, nBase,
                   c0, cend - c0, acc);

        // Atomic-add epilogue (out pre-initialized with bias by prep)
#pragma unroll
        for (int nt = 0; nt < 8; nt++) {
            int col = nBase + wn * 64 + nt * 8 + tc;
#pragma unroll
            for (int mt = 0; mt < 4; mt++) {
                int r0 = mBase + wm * 64 + mt * 16 + tg;
                float* p0 = out + (size_t)r0 * OUT_DIM + col;
                float* p1 = out + (size_t)(r0 + 8) * OUT_DIM + col;
                atomicAdd(p0,     acc[mt][nt][0]);
                atomicAdd(p0 + 1, acc[mt][nt][1]);
                atomicAdd(p1,     acc[mt][nt][2]);
                atomicAdd(p1 + 1, acc[mt][nt][3]);
            }
        }
        __syncthreads();   // all warps done before next segment reuses smem
        u0 = (t << 6) + cend;
    }
}

// ---------------------------------------------------------------------------
// kernel_launch
// ---------------------------------------------------------------------------
extern "C" void kernel_launch(void* const* d_in, const int* in_sizes, int n_in,
                              void* d_out, int out_size)
{
    const float* x      = (const float*)d_in[0];
    const float* phase  = (const float*)d_in[1];
    const float* w      = (const float*)d_in[2];
    const float* biases = (const float*)d_in[3];
    const float* basis  = (const float*)d_in[4];
    float* out = (float*)d_out;

    static bool attr_set = false;
    if (!attr_set) {
        cudaFuncSetAttribute(gemm_kernel,
                             cudaFuncAttributeMaxDynamicSharedMemorySize,
                             SMEM_TOTAL);
        attr_set = true;
    }

    prep_kernel<<<BATCH / 2 + 2048, 256>>>(x, phase, basis, w, biases, out);
    gemm_kernel<<<NBLOCKS, NTHREADS, SMEM_TOTAL>>>(out);
}